// round 10
// baseline (speedup 1.0000x reference)
#include <cuda_runtime.h>
#include <cuda_bf16.h>

// Problem constants
#define T_STEPS 1000
#define T_MAIN  990            // readout tail covers [990, 1000)
#define BATCH   256
#define HID     512
#define NIN     3
#define NOUT    2
#define BH      (BATCH * HID)             // 131072
#define SPK_ELEMS ((size_t)T_STEPS * BH)  // 131,072,000

#define BETA    0.8f
#define THRESH  1.0f

// ---------------------------------------------------------------------------
// Single fused kernel (R3 champion layout).
// Grid: 256 blocks (one per batch element b). 128 threads; each thread owns
// 4 consecutive hidden units h = tid*4..tid*4+3 -> one STG.128 spike store
// per timestep (block writes a contiguous 2KB row slice per t). x[:, b, :]
// staged in shared, padded to float4 rows -> one broadcast LDS.128 per step.
// Readout over the last 10 steps fused: register partials + block reduction.
// Main loop unrolled 4x so ptxas batches 4 independent STG.128s per warp.
// ---------------------------------------------------------------------------
__global__ __launch_bounds__(128)
void snn_fused_kernel(const float* __restrict__ x,     // [T, B, 3]
                      const float* __restrict__ W1,    // [512, 3]
                      const float* __restrict__ W2,    // [2, 512]
                      float* __restrict__ spk_out,     // [T, B, 512]
                      float* __restrict__ avg_out)     // [B, 2]
{
    __shared__ float sx[T_STEPS * 4];   // 16 KB, x rows padded 3 -> 4
    __shared__ float red[4][20];
    __shared__ float tot[20];

    const int b    = blockIdx.x;
    const int tid  = threadIdx.x;
    const int lane = tid & 31;
    const int wid  = tid >> 5;
    const int h0   = tid * 4;

    // Stage x[:, b, :] into shared. Thread handles rows t = tid, tid+128, ...
    // (3 scalar GMEM loads + 3 STS per row; no integer division).
    {
        const float* src = x + (size_t)tid * (BATCH * NIN) + b * NIN;
        float* dst = sx + tid * 4;
        for (int t = tid; t < T_STEPS; t += 128) {
            dst[0] = src[0];
            dst[1] = src[1];
            dst[2] = src[2];
            src += (size_t)128 * (BATCH * NIN);
            dst += 128 * 4;
        }
    }
    __syncthreads();

    // W1 rows for the 4 owned hidden units: 12 contiguous floats, 16B aligned
    const float4 w1a = reinterpret_cast<const float4*>(W1 + h0 * 3)[0];
    const float4 w1b = reinterpret_cast<const float4*>(W1 + h0 * 3)[1];
    const float4 w1c = reinterpret_cast<const float4*>(W1 + h0 * 3)[2];
    const float wA0 = w1a.x, wA1 = w1a.y, wA2 = w1a.z;
    const float wB0 = w1a.w, wB1 = w1b.x, wB2 = w1b.y;
    const float wC0 = w1b.z, wC1 = w1b.w, wC2 = w1c.x;
    const float wD0 = w1c.y, wD1 = w1c.z, wD2 = w1c.w;

    const float4* __restrict__ sx4 = reinterpret_cast<const float4*>(sx);
    float4* __restrict__ out = reinterpret_cast<float4*>(spk_out + (size_t)b * HID + h0);

    float m0 = 0.0f, m1 = 0.0f, m2 = 0.0f, m3 = 0.0f;
    bool  p0 = false, p1 = false, p2 = false, p3 = false;  // reset preds (prev mem)

    // ---- main scan: t in [0, 990) ----
    #pragma unroll 4
    for (int t = 0; t < T_MAIN; ++t) {
        const float4 xv = sx4[t];
        const float c0 = fmaf(xv.z, wA2, fmaf(xv.y, wA1, xv.x * wA0));
        const float c1 = fmaf(xv.z, wB2, fmaf(xv.y, wB1, xv.x * wB0));
        const float c2 = fmaf(xv.z, wC2, fmaf(xv.y, wC1, xv.x * wC0));
        const float c3 = fmaf(xv.z, wD2, fmaf(xv.y, wD1, xv.x * wD0));
        // exact reference: mem_new = (beta*mem + cur) * (1 - reset_prev)
        m0 = p0 ? 0.0f : fmaf(BETA, m0, c0);
        m1 = p1 ? 0.0f : fmaf(BETA, m1, c1);
        m2 = p2 ? 0.0f : fmaf(BETA, m2, c2);
        m3 = p3 ? 0.0f : fmaf(BETA, m3, c3);
        p0 = m0 > THRESH; p1 = m1 > THRESH;
        p2 = m2 > THRESH; p3 = m3 > THRESH;
        float4 sp;
        sp.x = p0 ? 1.0f : 0.0f;
        sp.y = p1 ? 1.0f : 0.0f;
        sp.z = p2 ? 1.0f : 0.0f;
        sp.w = p3 ? 1.0f : 0.0f;
        __stcs(out + (size_t)t * (BH / 4), sp);   // streaming STG.128
    }

    // ---- tail: t in [990, 1000), store spikes + accumulate readout ----
    const float4 w2o0 = reinterpret_cast<const float4*>(W2 + h0)[0];
    const float4 w2o1 = reinterpret_cast<const float4*>(W2 + HID + h0)[0];
    float acc[20];

    #pragma unroll
    for (int k = 0; k < 10; ++k) {
        const int t = T_MAIN + k;
        const float4 xv = sx4[t];
        const float c0 = fmaf(xv.z, wA2, fmaf(xv.y, wA1, xv.x * wA0));
        const float c1 = fmaf(xv.z, wB2, fmaf(xv.y, wB1, xv.x * wB0));
        const float c2 = fmaf(xv.z, wC2, fmaf(xv.y, wC1, xv.x * wC0));
        const float c3 = fmaf(xv.z, wD2, fmaf(xv.y, wD1, xv.x * wD0));
        m0 = p0 ? 0.0f : fmaf(BETA, m0, c0);
        m1 = p1 ? 0.0f : fmaf(BETA, m1, c1);
        m2 = p2 ? 0.0f : fmaf(BETA, m2, c2);
        m3 = p3 ? 0.0f : fmaf(BETA, m3, c3);
        p0 = m0 > THRESH; p1 = m1 > THRESH;
        p2 = m2 > THRESH; p3 = m3 > THRESH;
        float4 sp;
        sp.x = p0 ? 1.0f : 0.0f;
        sp.y = p1 ? 1.0f : 0.0f;
        sp.z = p2 ? 1.0f : 0.0f;
        sp.w = p3 ? 1.0f : 0.0f;
        __stcs(out + (size_t)t * (BH / 4), sp);

        float q0 = sp.x * w2o0.x; q0 = fmaf(sp.y, w2o0.y, q0);
        q0 = fmaf(sp.z, w2o0.z, q0); q0 = fmaf(sp.w, w2o0.w, q0);
        float q1 = sp.x * w2o1.x; q1 = fmaf(sp.y, w2o1.y, q1);
        q1 = fmaf(sp.z, w2o1.z, q1); q1 = fmaf(sp.w, w2o1.w, q1);
        acc[2 * k + 0] = q0;
        acc[2 * k + 1] = q1;
    }

    // ---- block reduction of the 20 partials ----
    #pragma unroll
    for (int j = 0; j < 20; ++j) {
        #pragma unroll
        for (int off = 16; off > 0; off >>= 1)
            acc[j] += __shfl_xor_sync(0xFFFFFFFFu, acc[j], off);
    }
    if (lane == 0) {
        #pragma unroll
        for (int j = 0; j < 20; ++j) red[wid][j] = acc[j];
    }
    __syncthreads();

    if (tid < 20)
        tot[tid] = red[0][tid] + red[1][tid] + red[2][tid] + red[3][tid];
    __syncthreads();

    if (tid < NOUT) {
        float s = 0.0f;
        #pragma unroll
        for (int k = 0; k < 10; ++k) {
            const float z = tot[2 * k + tid];
            s += 1.0f / (1.0f + expf(-z));
        }
        avg_out[b * NOUT + tid] = s * 0.1f;
    }
}

// ---------------------------------------------------------------------------
extern "C" void kernel_launch(void* const* d_in, const int* in_sizes, int n_in,
                              void* d_out, int out_size)
{
    const float* x  = (const float*)d_in[0];   // [1000, 256, 3]
    const float* W1 = (const float*)d_in[1];   // [512, 3]
    const float* W2 = (const float*)d_in[2];   // [2, 512]
    float* out = (float*)d_out;

    float* spk_out = out;                      // 131,072,000 floats
    float* avg_out = out + SPK_ELEMS;          // 512 floats

    snn_fused_kernel<<<BATCH, 128>>>(x, W1, W2, spk_out, avg_out);
}